// round 1
// baseline (speedup 1.0000x reference)
#include <cuda_runtime.h>
#include <cstdint>
#include <math.h>

// Problem constants (fixed by the reference)
#define NUM_K    1024      // primitives / codebook size
#define NUM_ROWS 32768     // 8 * 4096 tokens
#define DIM_D    1024      // embedding dim
#define N_ELEMS  33554432u // NUM_ROWS * NUM_K  (< 2^32 -> counter hi word = 0)

// scratch: activation counts (zeroed via cudaMemsetAsync each launch)
__device__ int g_counts[NUM_K];

// ---------------------------------------------------------------------------
// Threefry-2x32, 20 rounds, key = (0, 42) (jax.random.key(42)).
// Partitionable-mode 32-bit harvest: counter=(hi64(i), lo64(i)); out = x0 ^ x1.
// ---------------------------------------------------------------------------
__device__ __forceinline__ uint32_t tf_rotl(uint32_t x, int r) {
    return (x << r) | (x >> (32 - r));
}

__device__ __forceinline__ uint32_t threefry_xor(uint32_t c0, uint32_t c1) {
    const uint32_t ks0 = 0u;
    const uint32_t ks1 = 42u;
    const uint32_t ks2 = 0x1BD11BDAu ^ 0u ^ 42u;
    uint32_t x0 = c0 + ks0;
    uint32_t x1 = c1 + ks1;
#define TF_R(r) { x0 += x1; x1 = tf_rotl(x1, (r)); x1 ^= x0; }
    TF_R(13) TF_R(15) TF_R(26) TF_R(6)
    x0 += ks1; x1 += ks2 + 1u;
    TF_R(17) TF_R(29) TF_R(16) TF_R(24)
    x0 += ks2; x1 += ks0 + 2u;
    TF_R(13) TF_R(15) TF_R(26) TF_R(6)
    x0 += ks0; x1 += ks1 + 3u;
    TF_R(17) TF_R(29) TF_R(16) TF_R(24)
    x0 += ks1; x1 += ks2 + 4u;
    TF_R(13) TF_R(15) TF_R(26) TF_R(6)
    x0 += ks2; x1 += ks0 + 5u;
#undef TF_R
    return x0 ^ x1;
}

// uniform in [tiny, 1): bits>>9 | 1.0f bits, bitcast, -1.0, clamp tiny
// gumbel = -log(-log(u)); accurate logf both times (match XLA to ~1-2 ulp)
__device__ __forceinline__ float gumbel_from_bits(uint32_t bits) {
    float f = __uint_as_float((bits >> 9) | 0x3f800000u) - 1.0f;
    float u = fmaxf(f, 1.17549435e-38f);
    float t = -logf(u);
    return -logf(t);
}

// ---------------------------------------------------------------------------
// One block per row: gumbel+argmax over K=1024, gather primitives[idx],
// write index (as float), atomic count.
// ---------------------------------------------------------------------------
__global__ __launch_bounds__(256, 4)
void vybn_fused_kernel(const float* __restrict__ logits,
                       const float* __restrict__ prim,
                       float* __restrict__ out,
                       long long out_elems) {
    const int row = blockIdx.x;
    const int t   = threadIdx.x;
    const int lane = t & 31;
    const int warp = t >> 5;

    // each thread handles k in [4t, 4t+4) — vectorized logits load
    const float4 lv = ((const float4*)(logits + (size_t)row * NUM_K))[t];
    const uint32_t base = (uint32_t)row * (uint32_t)NUM_K + (uint32_t)(4 * t);

    float z0, z1, z2, z3;
    {
        // counter hi word is 0 (total elements < 2^32)
        uint32_t b0 = threefry_xor(0u, base + 0u);
        uint32_t b1 = threefry_xor(0u, base + 1u);
        uint32_t b2 = threefry_xor(0u, base + 2u);
        uint32_t b3 = threefry_xor(0u, base + 3u);
        z0 = lv.x + gumbel_from_bits(b0);
        z1 = lv.y + gumbel_from_bits(b1);
        z2 = lv.z + gumbel_from_bits(b2);
        z3 = lv.w + gumbel_from_bits(b3);
    }

    // local argmax with first-occurrence tie-break (ascending index, strict >)
    float best = z0; int bidx = 4 * t;
    if (z1 > best) { best = z1; bidx = 4 * t + 1; }
    if (z2 > best) { best = z2; bidx = 4 * t + 2; }
    if (z3 > best) { best = z3; bidx = 4 * t + 3; }

    // warp reduce (ties -> lower index)
    #pragma unroll
    for (int off = 16; off > 0; off >>= 1) {
        float ov = __shfl_down_sync(0xFFFFFFFFu, best, off);
        int   oi = __shfl_down_sync(0xFFFFFFFFu, bidx, off);
        if (ov > best || (ov == best && oi < bidx)) { best = ov; bidx = oi; }
    }

    __shared__ float swv[8];
    __shared__ int   swi[8];
    __shared__ int   s_idx;
    if (lane == 0) { swv[warp] = best; swi[warp] = bidx; }
    __syncthreads();

    if (t == 0) {
        best = swv[0]; bidx = swi[0];
        #pragma unroll
        for (int w = 1; w < 8; w++) {
            float ov = swv[w]; int oi = swi[w];
            if (ov > best || (ov == best && oi < bidx)) { best = ov; bidx = oi; }
        }
        s_idx = bidx;
        atomicAdd(&g_counts[bidx], 1);
        // indices output (as float) right after embeddings
        long long ioff = (long long)NUM_ROWS * DIM_D + row;
        if (ioff < out_elems) out[ioff] = (float)bidx;
    }
    __syncthreads();

    const int idx = s_idx;
    // embeddings row = primitives[idx] exactly (hard one-hot forward)
    float4 v = ((const float4*)(prim + (size_t)idx * DIM_D))[t];
    ((float4*)(out + (size_t)row * DIM_D))[t] = v;
}

__global__ void vybn_counts_kernel(float* __restrict__ out, long long out_elems) {
    int k = threadIdx.x + blockIdx.x * blockDim.x;
    if (k < NUM_K) {
        long long off = (long long)NUM_ROWS * DIM_D + NUM_ROWS + k;
        if (off < out_elems) out[off] = (float)g_counts[k];
    }
}

extern "C" void kernel_launch(void* const* d_in, const int* in_sizes, int n_in,
                              void* d_out, int out_size) {
    const float* logits = (const float*)d_in[0];
    const float* prim   = (const float*)d_in[1];
    // defensive: metadata order should be (logits, primitives); swap if sizes say otherwise
    if (n_in >= 2 && in_sizes[0] < in_sizes[1]) {
        const float* tmp = logits; logits = prim; prim = tmp;
    }
    float* out = (float*)d_out;

    void* cptr = nullptr;
    cudaGetSymbolAddress(&cptr, g_counts);
    cudaMemsetAsync(cptr, 0, sizeof(int) * NUM_K, 0);

    vybn_fused_kernel<<<NUM_ROWS, 256>>>(logits, prim, out, (long long)out_size);
    vybn_counts_kernel<<<1, NUM_K>>>(out, (long long)out_size);
}

// round 3
// speedup vs baseline: 1.0887x; 1.0887x over previous
#include <cuda_runtime.h>
#include <cstdint>
#include <math.h>

// Problem constants (fixed by the reference)
#define NUM_K    1024      // primitives / codebook size
#define NUM_ROWS 32768     // 8 * 4096 tokens
#define DIM_D    1024      // embedding dim

#define TINY_F   1.17549435e-38f
#define LN2_F    0.693147180559945f
#define T_SMALL  4e-3f     // below this, MUFU relative error on t blows up -> exact path
#define CAND_EPS 3e-4f     // 2x proven |z_approx - z_exact| bound (<=9e-5) with margin
#define NEG_INF  __int_as_float(0xff800000)

// scratch: activation counts (zeroed via cudaMemsetAsync each launch)
__device__ int g_counts[NUM_K];

// ---------------------------------------------------------------------------
// Threefry-2x32, 20 rounds, key = (0, 42) (jax.random.key(42)).
// Partitionable-mode 32-bit harvest: counter=(0, elem_idx); out = x0 ^ x1.
// ---------------------------------------------------------------------------
__device__ __forceinline__ uint32_t tf_rotl(uint32_t x, int r) {
    return (x << r) | (x >> (32 - r));
}

__device__ __forceinline__ uint32_t threefry_xor(uint32_t c0, uint32_t c1) {
    const uint32_t ks0 = 0u;
    const uint32_t ks1 = 42u;
    const uint32_t ks2 = 0x1BD11BDAu ^ 0u ^ 42u;
    uint32_t x0 = c0 + ks0;
    uint32_t x1 = c1 + ks1;
#define TF_R(r) { x0 += x1; x1 = tf_rotl(x1, (r)); x1 ^= x0; }
    TF_R(13) TF_R(15) TF_R(26) TF_R(6)
    x0 += ks1; x1 += ks2 + 1u;
    TF_R(17) TF_R(29) TF_R(16) TF_R(24)
    x0 += ks2; x1 += ks0 + 2u;
    TF_R(13) TF_R(15) TF_R(26) TF_R(6)
    x0 += ks0; x1 += ks1 + 3u;
    TF_R(17) TF_R(29) TF_R(16) TF_R(24)
    x0 += ks1; x1 += ks2 + 4u;
    TF_R(13) TF_R(15) TF_R(26) TF_R(6)
    x0 += ks2; x1 += ks0 + 5u;
#undef TF_R
    return x0 ^ x1;
}

// Exact gumbel: identical formula/precision to the reference (XLA lowers log ->
// libdevice logf, same as CUDA accurate logf). u must already be clamped.
__device__ __forceinline__ float gumbel_exact(float u) {
    return -logf(-logf(u));
}

// ---------------------------------------------------------------------------
// One block per row.
// Phase 1: cheap MUFU-based z~ for all K, block max of z~.
// Phase 2: exact z (accurate logf) only for candidates within CAND_EPS of the
//          max; argmax over exact values (lower-index tie-break).
// Then gather primitives[idx] -> out, atomic count.
// ---------------------------------------------------------------------------
__global__ __launch_bounds__(256, 4)
void vybn_fused_kernel(const float* __restrict__ logits,
                       const float* __restrict__ prim,
                       float* __restrict__ out,
                       long long out_elems) {
    const int row  = blockIdx.x;
    const int t    = threadIdx.x;
    const int lane = t & 31;
    const int warp = t >> 5;

    // each thread handles k in [4t, 4t+4)
    const float4 lv = ((const float4*)(logits + (size_t)row * NUM_K))[t];
    const float lvi[4] = {lv.x, lv.y, lv.z, lv.w};
    const uint32_t base = (uint32_t)row * (uint32_t)NUM_K + (uint32_t)(4 * t);

    float u[4];   // clamped uniform, kept for the exact rescue path
    float za[4];  // z approx (exact for tiny-t elements)
    float zmax = NEG_INF;

    #pragma unroll
    for (int i = 0; i < 4; i++) {
        uint32_t bits = threefry_xor(0u, base + (uint32_t)i);
        float f = __uint_as_float((bits >> 9) | 0x3f800000u) - 1.0f;
        u[i] = fmaxf(f, TINY_F);
        // t~ = -ln(u) = log2(u) * (-ln2)   (MUFU.LG2 + FMUL)
        float tt = __log2f(u[i]) * (-LN2_F);
        float z;
        if (tt < T_SMALL) {
            // relative error of t~ too large here (u near 1) -> exact now,
            // so z~ carries zero error for these elements.
            z = lvi[i] + gumbel_exact(u[i]);
        } else {
            // g~ = -ln(t~) = log2(t~) * (-ln2); z~ = fma(log2(t~), -ln2, logit)
            z = fmaf(__log2f(tt), -LN2_F, lvi[i]);
        }
        za[i] = z;
        zmax = fmaxf(zmax, z);
    }

    // block max of z~ (values only)
    #pragma unroll
    for (int off = 16; off > 0; off >>= 1)
        zmax = fmaxf(zmax, __shfl_xor_sync(0xFFFFFFFFu, zmax, off));

    __shared__ float swv[8];
    __shared__ float swe[8];
    __shared__ int   swi[8];
    __shared__ int   s_idx;
    if (lane == 0) swv[warp] = zmax;
    __syncthreads();

    float gmax = swv[0];
    #pragma unroll
    for (int w = 1; w < 8; w++) gmax = fmaxf(gmax, swv[w]);
    const float thresh = gmax - CAND_EPS;

    // Phase 2: exact evaluation for candidates only
    float best = NEG_INF;
    int   bidx = 4 * t;
    #pragma unroll
    for (int i = 0; i < 4; i++) {
        if (za[i] >= thresh) {
            float ze = lvi[i] + gumbel_exact(u[i]);
            if (ze > best) { best = ze; bidx = 4 * t + i; }
        }
    }

    // warp argmax (ties -> lower index)
    #pragma unroll
    for (int off = 16; off > 0; off >>= 1) {
        float ov = __shfl_down_sync(0xFFFFFFFFu, best, off);
        int   oi = __shfl_down_sync(0xFFFFFFFFu, bidx, off);
        if (ov > best || (ov == best && oi < bidx)) { best = ov; bidx = oi; }
    }
    if (lane == 0) { swe[warp] = best; swi[warp] = bidx; }
    __syncthreads();

    if (t == 0) {
        best = swe[0]; bidx = swi[0];
        #pragma unroll
        for (int w = 1; w < 8; w++) {
            float ov = swe[w]; int oi = swi[w];
            if (ov > best || (ov == best && oi < bidx)) { best = ov; bidx = oi; }
        }
        s_idx = bidx;
        atomicAdd(&g_counts[bidx], 1);
        long long ioff = (long long)NUM_ROWS * DIM_D + row;
        if (ioff < out_elems) out[ioff] = (float)bidx;
    }
    __syncthreads();

    const int idx = s_idx;
    // embeddings row = primitives[idx] exactly (hard one-hot forward)
    float4 v = ((const float4*)(prim + (size_t)idx * DIM_D))[t];
    ((float4*)(out + (size_t)row * DIM_D))[t] = v;
}

__global__ void vybn_counts_kernel(float* __restrict__ out, long long out_elems) {
    int k = threadIdx.x + blockIdx.x * blockDim.x;
    if (k < NUM_K) {
        long long off = (long long)NUM_ROWS * DIM_D + NUM_ROWS + k;
        if (off < out_elems) out[off] = (float)g_counts[k];
    }
}

extern "C" void kernel_launch(void* const* d_in, const int* in_sizes, int n_in,
                              void* d_out, int out_size) {
    const float* logits = (const float*)d_in[0];
    const float* prim   = (const float*)d_in[1];
    if (n_in >= 2 && in_sizes[0] < in_sizes[1]) {
        const float* tmp = logits; logits = prim; prim = tmp;
    }
    float* out = (float*)d_out;

    void* cptr = nullptr;
    cudaGetSymbolAddress(&cptr, g_counts);
    cudaMemsetAsync(cptr, 0, sizeof(int) * NUM_K, 0);

    vybn_fused_kernel<<<NUM_ROWS, 256>>>(logits, prim, out, (long long)out_size);
    vybn_counts_kernel<<<1, NUM_K>>>(out, (long long)out_size);
}